// round 10
// baseline (speedup 1.0000x reference)
#include <cuda_runtime.h>
#include <cuda_bf16.h>
#include <cstdint>

#define BATCH    4096
#define MTILE    32
#define NBLOCKS  (BATCH / MTILE)   // 128
#define NTHREADS 512               // 16 warps: (mt:2) x (nc:8)
#define NCOLS    448               // 64 h * 7 j
#define B_BYTES  (NCOLS * 128)     // 57344 per split term

// Pre-converted B tiles (bf16 hi/lo), already in swizzled [n][128B] layout
__device__ __align__(16) unsigned char g_bh[B_BYTES];
__device__ __align__(16) unsigned char g_bl[B_BYTES];

// smem byte offsets
#define OFF_AH   0
#define OFF_AL   4096
#define OFF_BH   8192
#define OFF_BL   (OFF_BH + B_BYTES)        // 65536
#define OFF_P    (OFF_BL + B_BYTES)        // 122880  (64 x stride33 f32)
#define OFF_XP   (OFF_P + 64 * 33 * 4)     // (7 x stride33 f32)
#define OFF_RD   (OFF_XP + 7 * 33 * 4)
#define OFF_RED  (OFF_RD + 128)            // 16 warps x 16 rows f32
#define SMEM_BYTES (OFF_RED + 16 * 16 * 4 + 16)

static __device__ __forceinline__ uint32_t s2u(const void* p) {
    return (uint32_t)__cvta_generic_to_shared(p);
}
static __device__ __forceinline__ uint32_t packbf2(__nv_bfloat16 lo, __nv_bfloat16 hi) {
    __nv_bfloat162 t(lo, hi);
    return *reinterpret_cast<uint32_t*>(&t);
}
static __device__ __forceinline__ void bsplit(float v, __nv_bfloat16& h, __nv_bfloat16& l) {
    h = __float2bfloat16(v);
    l = __float2bfloat16(v - __bfloat162float(h));
}
static __device__ __forceinline__ void mma16816(float* d, const uint32_t* a,
                                                uint32_t b0, uint32_t b1) {
    asm("mma.sync.aligned.m16n8k16.row.col.f32.bf16.bf16.f32 "
        "{%0,%1,%2,%3}, {%4,%5,%6,%7}, {%8,%9}, {%0,%1,%2,%3};"
        : "+f"(d[0]), "+f"(d[1]), "+f"(d[2]), "+f"(d[3])
        : "r"(a[0]), "r"(a[1]), "r"(a[2]), "r"(a[3]), "r"(b0), "r"(b1));
}
static __device__ __forceinline__ void cpa16(uint32_t saddr, const void* gptr) {
    asm volatile("cp.async.cg.shared.global [%0], [%1], 16;"
                 :: "r"(saddr), "l"(__cvta_generic_to_global(gptr)) : "memory");
}

// ---- Prep: convert coeff once into swizzled bf16 hi/lo global tiles ----
__global__ void prep_kernel(const float* __restrict__ coeff) {
    int i = blockIdx.x * blockDim.x + threadIdx.x;
    if (i < 4096 * 7) {
        float v = coeff[i];
        int r = i / 7, j = i - r * 7;
        int n = (r >> 6) * 7 + j;
        int k = r & 63;
        __nv_bfloat16 vh, vl;
        bsplit(v, vh, vl);
        uint32_t cb = (uint32_t)(k * 2) ^ (uint32_t)((n & 7) << 4);
        *reinterpret_cast<__nv_bfloat16*>(g_bh + n * 128 + cb) = vh;
        *reinterpret_cast<__nv_bfloat16*>(g_bl + n * 128 + cb) = vl;
    }
}

__global__ void __launch_bounds__(NTHREADS, 1) anfis_hmma_kernel(
    const float* __restrict__ x, const float* __restrict__ a,
    const float* __restrict__ b, const float* __restrict__ c,
    float* __restrict__ out)
{
    extern __shared__ char smem[];
    const int tid  = threadIdx.x;
    const int lane = tid & 31;
    const int wid  = tid >> 5;
    const int b0   = blockIdx.x * MTILE;

    // ---- Kick off B tile copies (cp.async, overlapped with memberships) ----
    {
        const uint32_t sbh = s2u(smem + OFF_BH);
        const uint32_t sbl = s2u(smem + OFF_BL);
        #pragma unroll
        for (int it = 0; it < B_BYTES / (NTHREADS * 16); it++) {   // 7
            const uint32_t o = (uint32_t)(it * NTHREADS + tid) * 16;
            cpa16(sbh + o, g_bh + o);
            cpa16(sbl + o, g_bl + o);
        }
        asm volatile("cp.async.commit_group;" ::: "memory");
    }

    // ---- Memberships: warp 0 -> P/xp/rden tables, warp 1 -> A (Q) tiles ----
    if (wid < 2) {
        const int bl = lane;
        const int bb = b0 + bl;
        float xi[6], mm[6][4];
        float den = 1.0f;
        #pragma unroll
        for (int i = 0; i < 6; i++) {
            xi[i] = __ldg(&x[bb * 6 + i]);
            float s = 0.0f;
            #pragma unroll
            for (int k = 0; k < 4; k++) {
                float av = __ldg(&a[i * 4 + k]);
                float bv = __ldg(&b[i * 4 + k]);
                float cv = __ldg(&c[i * 4 + k]);
                float d  = (xi[i] - cv) / av;
                float d2 = d * d;
                float db = (bv == 2.0f) ? (d2 * d2) : __powf(d2, bv);
                float mv = 1.0f / (1.0f + db);
                mm[i][k] = mv;
                s += mv;
            }
            den *= s;
        }
        if (wid == 0) {
            float* Ps = reinterpret_cast<float*>(smem + OFF_P);
            float* Xs = reinterpret_cast<float*>(smem + OFF_XP);
            float* Rd = reinterpret_cast<float*>(smem + OFF_RD);
            #pragma unroll
            for (int j = 0; j < 6; j++) Xs[j * 33 + bl] = xi[j];
            Xs[6 * 33 + bl] = 1.0f;
            Rd[bl] = 1.0f / fmaxf(den, 1e-12f);
            float m01[16];
            #pragma unroll
            for (int u = 0; u < 4; u++)
                #pragma unroll
                for (int v = 0; v < 4; v++) m01[u * 4 + v] = mm[0][u] * mm[1][v];
            #pragma unroll
            for (int h = 0; h < 64; h++)
                Ps[h * 33 + bl] = m01[h >> 2] * mm[2][h & 3];
        } else {
            float m34[16];
            #pragma unroll
            for (int u = 0; u < 4; u++)
                #pragma unroll
                for (int v = 0; v < 4; v++) m34[u * 4 + v] = mm[3][u] * mm[4][v];
            #pragma unroll
            for (int l = 0; l < 64; l += 2) {
                float q0 = m34[l >> 2] * mm[5][l & 3];
                float q1 = m34[(l + 1) >> 2] * mm[5][(l + 1) & 3];
                __nv_bfloat16 h0, l0, h1, l1;
                bsplit(q0, h0, l0);
                bsplit(q1, h1, l1);
                uint32_t cb = (uint32_t)(l * 2) ^ (uint32_t)((bl & 7) << 4);
                *reinterpret_cast<uint32_t*>(smem + OFF_AH + bl * 128 + cb) = packbf2(h0, h1);
                *reinterpret_cast<uint32_t*>(smem + OFF_AL + bl * 128 + cb) = packbf2(l0, l1);
            }
        }
    }
    asm volatile("cp.async.wait_group 0;" ::: "memory");
    __syncthreads();

    // ---- HMMA mainloop: warp = (mtile, 56-col chunk); 7 ntiles x 3 terms ----
    const int mt = wid >> 3;        // 0..1
    const int nc = wid & 7;         // 0..7

    float acc[7][4];
    #pragma unroll
    for (int nt = 0; nt < 7; nt++)
        #pragma unroll
        for (int e = 0; e < 4; e++) acc[nt][e] = 0.0f;

    const int r  = lane >> 2;
    const int c4 = (lane & 3) * 4;
    const uint32_t rsw = (uint32_t)(r << 4);

    #pragma unroll
    for (int ks = 0; ks < 4; ks++) {
        const uint32_t cb0 = (uint32_t)(ks * 32 + c4) ^ rsw;
        const uint32_t cb1 = (uint32_t)(ks * 32 + c4 + 16) ^ rsw;
        uint32_t ah[4], al[4];
        {
            const int row = mt * 16 + r;
            ah[0] = *reinterpret_cast<const uint32_t*>(smem + OFF_AH + row * 128 + cb0);
            ah[1] = *reinterpret_cast<const uint32_t*>(smem + OFF_AH + (row + 8) * 128 + cb0);
            ah[2] = *reinterpret_cast<const uint32_t*>(smem + OFF_AH + row * 128 + cb1);
            ah[3] = *reinterpret_cast<const uint32_t*>(smem + OFF_AH + (row + 8) * 128 + cb1);
            al[0] = *reinterpret_cast<const uint32_t*>(smem + OFF_AL + row * 128 + cb0);
            al[1] = *reinterpret_cast<const uint32_t*>(smem + OFF_AL + (row + 8) * 128 + cb0);
            al[2] = *reinterpret_cast<const uint32_t*>(smem + OFF_AL + row * 128 + cb1);
            al[3] = *reinterpret_cast<const uint32_t*>(smem + OFF_AL + (row + 8) * 128 + cb1);
        }
        #pragma unroll
        for (int nt = 0; nt < 7; nt++) {
            const int n = nc * 56 + nt * 8 + r;       // n & 7 == r
            uint32_t bh0 = *reinterpret_cast<const uint32_t*>(smem + OFF_BH + n * 128 + cb0);
            uint32_t bh1 = *reinterpret_cast<const uint32_t*>(smem + OFF_BH + n * 128 + cb1);
            uint32_t bl0 = *reinterpret_cast<const uint32_t*>(smem + OFF_BL + n * 128 + cb0);
            uint32_t bl1 = *reinterpret_cast<const uint32_t*>(smem + OFF_BL + n * 128 + cb1);
            mma16816(acc[nt], ah, bh0, bh1);   // hi*hi
            mma16816(acc[nt], ah, bl0, bl1);   // hi*lo
            mma16816(acc[nt], al, bh0, bh1);   // lo*hi
        }
    }

    // ---- Epilogue: fold P * x_plus, reduce quads, stash per-warp rows ----
    {
        const float* Ps = reinterpret_cast<const float*>(smem + OFF_P);
        const float* Xs = reinterpret_cast<const float*>(smem + OFF_XP);
        float rsum[2] = {0.f, 0.f};
        #pragma unroll
        for (int nt = 0; nt < 7; nt++)
            #pragma unroll
            for (int e = 0; e < 4; e++) {
                const int row = mt * 16 + r + (e >> 1) * 8;
                const int u   = nt * 8 + 2 * (lane & 3) + (e & 1);
                const int h   = u / 7;
                const int j   = u - h * 7;
                float pv = Ps[(nc * 8 + h) * 33 + row];
                float xv = Xs[j * 33 + row];
                rsum[e >> 1] = fmaf(pv * xv, acc[nt][e], rsum[e >> 1]);
            }
        #pragma unroll
        for (int i = 0; i < 2; i++) {
            rsum[i] += __shfl_xor_sync(0xFFFFFFFFu, rsum[i], 1);
            rsum[i] += __shfl_xor_sync(0xFFFFFFFFu, rsum[i], 2);
        }
        if ((lane & 3) == 0) {
            float* red = reinterpret_cast<float*>(smem + OFF_RED);
            red[wid * 16 + r]     = rsum[0];
            red[wid * 16 + r + 8] = rsum[1];
        }
    }
    __syncthreads();

    // ---- Final: sum 8 n-chunk warps per row, normalize, store ----
    if (tid < MTILE) {
        const float* red = reinterpret_cast<const float*>(smem + OFF_RED);
        const float* Rd  = reinterpret_cast<const float*>(smem + OFF_RD);
        const int mtid = tid >> 4;
        const int rl   = tid & 15;
        float num = 0.0f;
        #pragma unroll
        for (int w = 0; w < 8; w++)
            num += red[(mtid * 8 + w) * 16 + rl];
        out[b0 + tid] = num * Rd[tid];
    }
}

extern "C" void kernel_launch(void* const* d_in, const int* in_sizes, int n_in,
                              void* d_out, int out_size) {
    const float* x     = (const float*)d_in[0];
    const float* a     = (const float*)d_in[1];
    const float* b     = (const float*)d_in[2];
    const float* c     = (const float*)d_in[3];
    const float* coeff = (const float*)d_in[4];
    // d_in[5] = mf_indices: full itertools.product enumeration; base-4 digit
    // decode is analytic, index tensor unused.
    float* out = (float*)d_out;

    static bool attr_set = false;
    if (!attr_set) {
        cudaFuncSetAttribute(anfis_hmma_kernel,
                             cudaFuncAttributeMaxDynamicSharedMemorySize, SMEM_BYTES);
        attr_set = true;
    }
    prep_kernel<<<(4096 * 7 + 255) / 256, 256>>>(coeff);
    anfis_hmma_kernel<<<NBLOCKS, NTHREADS, SMEM_BYTES>>>(x, a, b, c, out);
}

// round 11
// speedup vs baseline: 1.1253x; 1.1253x over previous
#include <cuda_runtime.h>
#include <cuda_bf16.h>
#include <cstdint>

#define BATCH    4096
#define MTILE    32
#define NBLOCKS  (BATCH / MTILE)   // 128
#define NTHREADS 512               // 16 warps: (mt:2) x (nc:8)

// B fragments pre-laid-out for HMMA: index f=((nc*4+ks)*7+nt), lane gets
// uint4 {bh0, bh1, bl0, bl1} at g_bfrag[f*32 + lane]. 4*56*32*16B = 114688 B.
__device__ __align__(16) uint4 g_bfrag[4 * 56 * 32];

// smem byte offsets (small now: A tiles + tables + reduce)
#define OFF_AH   0
#define OFF_AL   4096
#define OFF_P    8192                       // 64 x stride33 f32 = 8448
#define OFF_XP   (OFF_P + 64 * 33 * 4)      // 7 x stride33 f32
#define OFF_RD   (OFF_XP + 7 * 33 * 4)
#define OFF_RED  (OFF_RD + 128)             // 16 warps x 16 rows f32
#define SMEM_BYTES (OFF_RED + 16 * 16 * 4 + 16)

static __device__ __forceinline__ uint32_t packbf2(__nv_bfloat16 lo, __nv_bfloat16 hi) {
    __nv_bfloat162 t(lo, hi);
    return *reinterpret_cast<uint32_t*>(&t);
}
static __device__ __forceinline__ void bsplit(float v, __nv_bfloat16& h, __nv_bfloat16& l) {
    h = __float2bfloat16(v);
    l = __float2bfloat16(v - __bfloat162float(h));
}
static __device__ __forceinline__ void mma16816(float* d, const uint32_t* a,
                                                uint32_t b0, uint32_t b1) {
    asm("mma.sync.aligned.m16n8k16.row.col.f32.bf16.bf16.f32 "
        "{%0,%1,%2,%3}, {%4,%5,%6,%7}, {%8,%9}, {%0,%1,%2,%3};"
        : "+f"(d[0]), "+f"(d[1]), "+f"(d[2]), "+f"(d[3])
        : "r"(a[0]), "r"(a[1]), "r"(a[2]), "r"(a[3]), "r"(b0), "r"(b1));
}

// ---- Prep: coeff -> bf16 hi/lo fragments in exact HMMA lane layout ----
// B[n][k] with n = h*7+j (h = rule high digits, j = coeff element), k = rule
// low digits; B[n][k] = coeff[(h*64+k)*7 + j].
__global__ void prep_kernel(const float* __restrict__ coeff) {
    int i = blockIdx.x * blockDim.x + threadIdx.x;   // 7168 threads
    if (i >= 4 * 56 * 32) return;
    const int lane = i & 31;
    const int f    = i >> 5;
    const int nt   = f % 7;
    const int t2   = f / 7;
    const int ks   = t2 & 3;
    const int nc   = t2 >> 2;

    const int n  = nc * 56 + nt * 8 + (lane >> 2);
    const int h  = n / 7;
    const int j  = n - h * 7;
    const int k0 = ks * 16 + 2 * (lane & 3);

    float v0 = coeff[(h * 64 + k0) * 7 + j];
    float v1 = coeff[(h * 64 + k0 + 1) * 7 + j];
    float v2 = coeff[(h * 64 + k0 + 8) * 7 + j];
    float v3 = coeff[(h * 64 + k0 + 9) * 7 + j];

    __nv_bfloat16 h0, l0, h1, l1, h2, l2, h3, l3;
    bsplit(v0, h0, l0);
    bsplit(v1, h1, l1);
    bsplit(v2, h2, l2);
    bsplit(v3, h3, l3);

    uint4 o;
    o.x = packbf2(h0, h1);   // bh0: (k0, k0+1)
    o.y = packbf2(h2, h3);   // bh1: (k0+8, k0+9)
    o.z = packbf2(l0, l1);   // bl0
    o.w = packbf2(l2, l3);   // bl1
    g_bfrag[f * 32 + lane] = o;
}

__global__ void __launch_bounds__(NTHREADS, 1) anfis_hmma_kernel(
    const float* __restrict__ x, const float* __restrict__ a,
    const float* __restrict__ b, const float* __restrict__ c,
    float* __restrict__ out)
{
    extern __shared__ char smem[];
    const int tid  = threadIdx.x;
    const int lane = tid & 31;
    const int wid  = tid >> 5;
    const int b0   = blockIdx.x * MTILE;

    // ---- Memberships: warp 0 -> P/xp/rden tables, warp 1 -> A (Q) tiles ----
    if (wid < 2) {
        const int bl = lane;
        const int bb = b0 + bl;
        float xi[6], mm[6][4];
        float den = 1.0f;
        #pragma unroll
        for (int i = 0; i < 6; i++) {
            xi[i] = __ldg(&x[bb * 6 + i]);
            float s = 0.0f;
            #pragma unroll
            for (int k = 0; k < 4; k++) {
                float av = __ldg(&a[i * 4 + k]);
                float bv = __ldg(&b[i * 4 + k]);
                float cv = __ldg(&c[i * 4 + k]);
                float d  = (xi[i] - cv) / av;
                float d2 = d * d;
                float db = (bv == 2.0f) ? (d2 * d2) : __powf(d2, bv);
                float mv = 1.0f / (1.0f + db);
                mm[i][k] = mv;
                s += mv;
            }
            den *= s;
        }
        if (wid == 0) {
            float* Ps = reinterpret_cast<float*>(smem + OFF_P);
            float* Xs = reinterpret_cast<float*>(smem + OFF_XP);
            float* Rd = reinterpret_cast<float*>(smem + OFF_RD);
            #pragma unroll
            for (int j = 0; j < 6; j++) Xs[j * 33 + bl] = xi[j];
            Xs[6 * 33 + bl] = 1.0f;
            Rd[bl] = 1.0f / fmaxf(den, 1e-12f);
            float m01[16];
            #pragma unroll
            for (int u = 0; u < 4; u++)
                #pragma unroll
                for (int v = 0; v < 4; v++) m01[u * 4 + v] = mm[0][u] * mm[1][v];
            #pragma unroll
            for (int h = 0; h < 64; h++)
                Ps[h * 33 + bl] = m01[h >> 2] * mm[2][h & 3];
        } else {
            // A tiles: row bl = Q values over 64 low digits, bf16 hi/lo, swizzled
            float m34[16];
            #pragma unroll
            for (int u = 0; u < 4; u++)
                #pragma unroll
                for (int v = 0; v < 4; v++) m34[u * 4 + v] = mm[3][u] * mm[4][v];
            #pragma unroll
            for (int l = 0; l < 64; l += 2) {
                float q0 = m34[l >> 2] * mm[5][l & 3];
                float q1 = m34[(l + 1) >> 2] * mm[5][(l + 1) & 3];
                __nv_bfloat16 h0, l0, h1, l1;
                bsplit(q0, h0, l0);
                bsplit(q1, h1, l1);
                uint32_t cb = (uint32_t)(l * 2) ^ (uint32_t)((bl & 7) << 4);
                *reinterpret_cast<uint32_t*>(smem + OFF_AH + bl * 128 + cb) = packbf2(h0, h1);
                *reinterpret_cast<uint32_t*>(smem + OFF_AL + bl * 128 + cb) = packbf2(l0, l1);
            }
        }
    }
    __syncthreads();

    // ---- HMMA mainloop: warp = (mtile, 56-col chunk); B straight from L2 ----
    const int mt = wid >> 3;        // 0..1
    const int nc = wid & 7;         // 0..7

    float acc[7][4];
    #pragma unroll
    for (int nt = 0; nt < 7; nt++)
        #pragma unroll
        for (int e = 0; e < 4; e++) acc[nt][e] = 0.0f;

    const int r  = lane >> 2;
    const int c4 = (lane & 3) * 4;
    const uint32_t rsw = (uint32_t)(r << 4);

    #pragma unroll
    for (int ks = 0; ks < 4; ks++) {
        // B fragments for this (nc, ks): 7 coalesced LDG.128, batched for MLP
        uint4 bf[7];
        #pragma unroll
        for (int nt = 0; nt < 7; nt++)
            bf[nt] = __ldg(&g_bfrag[(((nc * 4 + ks) * 7 + nt) * 32) + lane]);

        // A fragments from smem (hi & lo)
        const uint32_t cb0 = (uint32_t)(ks * 32 + c4) ^ rsw;
        const uint32_t cb1 = (uint32_t)(ks * 32 + c4 + 16) ^ rsw;
        uint32_t ah[4], al[4];
        {
            const int row = mt * 16 + r;
            ah[0] = *reinterpret_cast<const uint32_t*>(smem + OFF_AH + row * 128 + cb0);
            ah[1] = *reinterpret_cast<const uint32_t*>(smem + OFF_AH + (row + 8) * 128 + cb0);
            ah[2] = *reinterpret_cast<const uint32_t*>(smem + OFF_AH + row * 128 + cb1);
            ah[3] = *reinterpret_cast<const uint32_t*>(smem + OFF_AH + (row + 8) * 128 + cb1);
            al[0] = *reinterpret_cast<const uint32_t*>(smem + OFF_AL + row * 128 + cb0);
            al[1] = *reinterpret_cast<const uint32_t*>(smem + OFF_AL + (row + 8) * 128 + cb0);
            al[2] = *reinterpret_cast<const uint32_t*>(smem + OFF_AL + row * 128 + cb1);
            al[3] = *reinterpret_cast<const uint32_t*>(smem + OFF_AL + (row + 8) * 128 + cb1);
        }
        #pragma unroll
        for (int nt = 0; nt < 7; nt++) {
            mma16816(acc[nt], ah, bf[nt].x, bf[nt].y);   // hi*hi
            mma16816(acc[nt], ah, bf[nt].z, bf[nt].w);   // hi*lo
            mma16816(acc[nt], al, bf[nt].x, bf[nt].y);   // lo*hi
        }
    }

    // ---- Epilogue: fold P * x_plus, reduce quads, stash per-warp rows ----
    {
        const float* Ps = reinterpret_cast<const float*>(smem + OFF_P);
        const float* Xs = reinterpret_cast<const float*>(smem + OFF_XP);
        float rsum[2] = {0.f, 0.f};
        #pragma unroll
        for (int nt = 0; nt < 7; nt++)
            #pragma unroll
            for (int e = 0; e < 4; e++) {
                const int row = mt * 16 + r + (e >> 1) * 8;
                const int u   = nt * 8 + 2 * (lane & 3) + (e & 1);
                const int h   = u / 7;
                const int j   = u - h * 7;
                float pv = Ps[(nc * 8 + h) * 33 + row];
                float xv = Xs[j * 33 + row];
                rsum[e >> 1] = fmaf(pv * xv, acc[nt][e], rsum[e >> 1]);
            }
        #pragma unroll
        for (int i = 0; i < 2; i++) {
            rsum[i] += __shfl_xor_sync(0xFFFFFFFFu, rsum[i], 1);
            rsum[i] += __shfl_xor_sync(0xFFFFFFFFu, rsum[i], 2);
        }
        if ((lane & 3) == 0) {
            float* red = reinterpret_cast<float*>(smem + OFF_RED);
            red[wid * 16 + r]     = rsum[0];
            red[wid * 16 + r + 8] = rsum[1];
        }
    }
    __syncthreads();

    // ---- Final: sum 8 n-chunk warps per row, normalize, store ----
    if (tid < MTILE) {
        const float* red = reinterpret_cast<const float*>(smem + OFF_RED);
        const float* Rd  = reinterpret_cast<const float*>(smem + OFF_RD);
        const int mtid = tid >> 4;
        const int rl   = tid & 15;
        float num = 0.0f;
        #pragma unroll
        for (int w = 0; w < 8; w++)
            num += red[(mtid * 8 + w) * 16 + rl];
        out[b0 + tid] = num * Rd[tid];
    }
}

extern "C" void kernel_launch(void* const* d_in, const int* in_sizes, int n_in,
                              void* d_out, int out_size) {
    const float* x     = (const float*)d_in[0];
    const float* a     = (const float*)d_in[1];
    const float* b     = (const float*)d_in[2];
    const float* c     = (const float*)d_in[3];
    const float* coeff = (const float*)d_in[4];
    // d_in[5] = mf_indices: full itertools.product enumeration; base-4 digit
    // decode is analytic, index tensor unused.
    float* out = (float*)d_out;

    prep_kernel<<<(4 * 56 * 32 + 255) / 256, 256>>>(coeff);
    anfis_hmma_kernel<<<NBLOCKS, NTHREADS, SMEM_BYTES>>>(x, a, b, c, out);
}

// round 12
// speedup vs baseline: 1.3314x; 1.1831x over previous
#include <cuda_runtime.h>
#include <cuda_bf16.h>
#include <cstdint>

#define BATCH    4096
#define MTILE    32
#define NBLOCKS  (BATCH / MTILE)   // 128
#define NTHREADS 512               // 16 warps: (mt:2) x (nc:8)

// B fragments pre-laid-out for HMMA: index f=((nc*4+ks)*7+nt), lane gets
// uint4 {bh0, bh1, bl0, bl1} at g_bfrag[f*32 + lane]. 114688 B, L2-resident.
__device__ __align__(16) uint4 g_bfrag[4 * 56 * 32];

// smem byte offsets
#define OFF_AH   0
#define OFF_AL   4096
#define OFF_P    8192                       // 64 x stride33 f32
#define OFF_XP   (OFF_P + 64 * 33 * 4)      // 7 x stride33 f32
#define OFF_RD   (OFF_XP + 7 * 33 * 4)
#define OFF_RED  (OFF_RD + 128)             // 16 warps x 16 rows f32
#define OFF_MSM  (OFF_RED + 16 * 16 * 4)    // 24 x 32 f32 memberships
#define OFF_SS   (OFF_MSM + 24 * 32 * 4)    // 6 x 32 f32 row sums
#define SMEM_BYTES (OFF_SS + 6 * 32 * 4 + 16)

static __device__ __forceinline__ uint32_t packbf2(__nv_bfloat16 lo, __nv_bfloat16 hi) {
    __nv_bfloat162 t(lo, hi);
    return *reinterpret_cast<uint32_t*>(&t);
}
static __device__ __forceinline__ void bsplit(float v, __nv_bfloat16& h, __nv_bfloat16& l) {
    h = __float2bfloat16(v);
    l = __float2bfloat16(v - __bfloat162float(h));
}
static __device__ __forceinline__ void mma16816(float* d, const uint32_t* a,
                                                uint32_t b0, uint32_t b1) {
    asm("mma.sync.aligned.m16n8k16.row.col.f32.bf16.bf16.f32 "
        "{%0,%1,%2,%3}, {%4,%5,%6,%7}, {%8,%9}, {%0,%1,%2,%3};"
        : "+f"(d[0]), "+f"(d[1]), "+f"(d[2]), "+f"(d[3])
        : "r"(a[0]), "r"(a[1]), "r"(a[2]), "r"(a[3]), "r"(b0), "r"(b1));
}

// ---- Prep: coeff -> bf16 hi/lo fragments in exact HMMA lane layout ----
__global__ void prep_kernel(const float* __restrict__ coeff) {
    int i = blockIdx.x * blockDim.x + threadIdx.x;   // 7168 threads
    if (i >= 4 * 56 * 32) return;
    const int lane = i & 31;
    const int f    = i >> 5;
    const int nt   = f % 7;
    const int t2   = f / 7;
    const int ks   = t2 & 3;
    const int nc   = t2 >> 2;

    const int n  = nc * 56 + nt * 8 + (lane >> 2);
    const int h  = n / 7;
    const int j  = n - h * 7;
    const int k0 = ks * 16 + 2 * (lane & 3);

    float v0 = coeff[(h * 64 + k0) * 7 + j];
    float v1 = coeff[(h * 64 + k0 + 1) * 7 + j];
    float v2 = coeff[(h * 64 + k0 + 8) * 7 + j];
    float v3 = coeff[(h * 64 + k0 + 9) * 7 + j];

    __nv_bfloat16 h0, l0, h1, l1, h2, l2, h3, l3;
    bsplit(v0, h0, l0);
    bsplit(v1, h1, l1);
    bsplit(v2, h2, l2);
    bsplit(v3, h3, l3);

    uint4 o;
    o.x = packbf2(h0, h1);
    o.y = packbf2(h2, h3);
    o.z = packbf2(l0, l1);
    o.w = packbf2(l2, l3);
    g_bfrag[f * 32 + lane] = o;
}

__global__ void __launch_bounds__(NTHREADS, 1) anfis_hmma_kernel(
    const float* __restrict__ x, const float* __restrict__ a,
    const float* __restrict__ b, const float* __restrict__ c,
    float* __restrict__ out)
{
    extern __shared__ char smem[];
    float* Ps  = reinterpret_cast<float*>(smem + OFF_P);
    float* Xs  = reinterpret_cast<float*>(smem + OFF_XP);
    float* Rd  = reinterpret_cast<float*>(smem + OFF_RD);
    float* Msm = reinterpret_cast<float*>(smem + OFF_MSM);  // [(i*4+k)*32 + bl]
    float* Ss  = reinterpret_cast<float*>(smem + OFF_SS);   // [i*32 + bl]

    const int tid  = threadIdx.x;
    const int lane = tid & 31;
    const int wid  = tid >> 5;
    const int b0   = blockIdx.x * MTILE;

    // ---- Phase A: memberships, (b,i) task per thread (192 threads) ----
    if (tid < 192) {
        const int bl = tid & 31;
        const int i  = tid >> 5;       // 0..5
        float xi = __ldg(&x[(b0 + bl) * 6 + i]);
        Xs[i * 33 + bl] = xi;
        float s = 0.0f;
        #pragma unroll
        for (int k = 0; k < 4; k++) {
            float av = __ldg(&a[i * 4 + k]);
            float bv = __ldg(&b[i * 4 + k]);
            float cv = __ldg(&c[i * 4 + k]);
            float d  = __fdividef(xi - cv, av);
            float d2 = d * d;
            float db = (bv == 2.0f) ? (d2 * d2) : __powf(d2, bv);
            float mv = __fdividef(1.0f, 1.0f + db);
            Msm[(i * 4 + k) * 32 + bl] = mv;
            s += mv;
        }
        Ss[i * 32 + bl] = s;
    }
    __syncthreads();

    // ---- Phase B: den, P table, A tiles — all 512 threads in parallel ----
    if (tid < 32) {
        float den = Ss[tid] * Ss[32 + tid] * Ss[64 + tid]
                  * Ss[96 + tid] * Ss[128 + tid] * Ss[160 + tid];
        Rd[tid] = __fdividef(1.0f, fmaxf(den, 1e-12f));
        Xs[6 * 33 + tid] = 1.0f;
    }
    // P table: 2048 entries, 4 per thread (bl == lane -> conflict-free)
    #pragma unroll
    for (int q = 0; q < 4; q++) {
        const int e  = tid + q * 512;
        const int h  = e >> 5;
        const int bl = e & 31;
        Ps[h * 33 + bl] = Msm[(0 + ((h >> 4) & 3)) * 32 + bl]
                        * Msm[(4 + ((h >> 2) & 3)) * 32 + bl]
                        * Msm[(8 + (h & 3)) * 32 + bl];
    }
    // A tiles: 1024 (bl, l-pair) tasks, 2 per thread
    #pragma unroll
    for (int q = 0; q < 2; q++) {
        const int u  = tid + q * 512;
        const int bl = u & 31;
        const int l  = (u >> 5) * 2;   // even l
        float tt = Msm[(12 + ((l >> 4) & 3)) * 32 + bl]
                 * Msm[(16 + ((l >> 2) & 3)) * 32 + bl];
        float q0 = tt * Msm[(20 + (l & 3)) * 32 + bl];
        float q1 = tt * Msm[(20 + ((l & 3) + 1)) * 32 + bl];
        __nv_bfloat16 h0, l0, h1, l1;
        bsplit(q0, h0, l0);
        bsplit(q1, h1, l1);
        uint32_t cb = (uint32_t)(l * 2) ^ (uint32_t)((bl & 7) << 4);
        *reinterpret_cast<uint32_t*>(smem + OFF_AH + bl * 128 + cb) = packbf2(h0, h1);
        *reinterpret_cast<uint32_t*>(smem + OFF_AL + bl * 128 + cb) = packbf2(l0, l1);
    }
    __syncthreads();

    // ---- HMMA mainloop: warp = (mtile, 56-col chunk); double-buffered B ----
    const int mt = wid >> 3;
    const int nc = wid & 7;

    float acc[7][4];
    #pragma unroll
    for (int nt = 0; nt < 7; nt++)
        #pragma unroll
        for (int e = 0; e < 4; e++) acc[nt][e] = 0.0f;

    const int r  = lane >> 2;
    const int c4 = (lane & 3) * 4;
    const uint32_t rsw = (uint32_t)(r << 4);

    uint4 bf[2][7];
    #pragma unroll
    for (int nt = 0; nt < 7; nt++)
        bf[0][nt] = __ldg(&g_bfrag[(((nc * 4 + 0) * 7 + nt) * 32) + lane]);

    #pragma unroll
    for (int ks = 0; ks < 4; ks++) {
        const int cur = ks & 1;
        if (ks < 3) {
            #pragma unroll
            for (int nt = 0; nt < 7; nt++)
                bf[cur ^ 1][nt] =
                    __ldg(&g_bfrag[(((nc * 4 + ks + 1) * 7 + nt) * 32) + lane]);
        }
        const uint32_t cb0 = (uint32_t)(ks * 32 + c4) ^ rsw;
        const uint32_t cb1 = (uint32_t)(ks * 32 + c4 + 16) ^ rsw;
        uint32_t ah[4], al[4];
        {
            const int row = mt * 16 + r;
            ah[0] = *reinterpret_cast<const uint32_t*>(smem + OFF_AH + row * 128 + cb0);
            ah[1] = *reinterpret_cast<const uint32_t*>(smem + OFF_AH + (row + 8) * 128 + cb0);
            ah[2] = *reinterpret_cast<const uint32_t*>(smem + OFF_AH + row * 128 + cb1);
            ah[3] = *reinterpret_cast<const uint32_t*>(smem + OFF_AH + (row + 8) * 128 + cb1);
            al[0] = *reinterpret_cast<const uint32_t*>(smem + OFF_AL + row * 128 + cb0);
            al[1] = *reinterpret_cast<const uint32_t*>(smem + OFF_AL + (row + 8) * 128 + cb0);
            al[2] = *reinterpret_cast<const uint32_t*>(smem + OFF_AL + row * 128 + cb1);
            al[3] = *reinterpret_cast<const uint32_t*>(smem + OFF_AL + (row + 8) * 128 + cb1);
        }
        #pragma unroll
        for (int nt = 0; nt < 7; nt++) {
            mma16816(acc[nt], ah, bf[cur][nt].x, bf[cur][nt].y);   // hi*hi
            mma16816(acc[nt], ah, bf[cur][nt].z, bf[cur][nt].w);   // hi*lo
            mma16816(acc[nt], al, bf[cur][nt].x, bf[cur][nt].y);   // lo*hi
        }
    }

    // ---- Epilogue: fold P * x_plus, reduce quads, stash per-warp rows ----
    {
        float rsum[2] = {0.f, 0.f};
        #pragma unroll
        for (int nt = 0; nt < 7; nt++)
            #pragma unroll
            for (int e = 0; e < 4; e++) {
                const int row = mt * 16 + r + (e >> 1) * 8;
                const int u   = nt * 8 + 2 * (lane & 3) + (e & 1);
                const int h   = u / 7;
                const int j   = u - h * 7;
                float pv = Ps[(nc * 8 + h) * 33 + row];
                float xv = Xs[j * 33 + row];
                rsum[e >> 1] = fmaf(pv * xv, acc[nt][e], rsum[e >> 1]);
            }
        #pragma unroll
        for (int i = 0; i < 2; i++) {
            rsum[i] += __shfl_xor_sync(0xFFFFFFFFu, rsum[i], 1);
            rsum[i] += __shfl_xor_sync(0xFFFFFFFFu, rsum[i], 2);
        }
        if ((lane & 3) == 0) {
            float* red = reinterpret_cast<float*>(smem + OFF_RED);
            red[wid * 16 + r]     = rsum[0];
            red[wid * 16 + r + 8] = rsum[1];
        }
    }
    __syncthreads();

    // ---- Final: sum 8 n-chunk warps per row, normalize, store ----
    if (tid < MTILE) {
        const float* red = reinterpret_cast<const float*>(smem + OFF_RED);
        const int mtid = tid >> 4;
        const int rl   = tid & 15;
        float num = 0.0f;
        #pragma unroll
        for (int w = 0; w < 8; w++)
            num += red[(mtid * 8 + w) * 16 + rl];
        out[b0 + tid] = num * Rd[tid];
    }
}

extern "C" void kernel_launch(void* const* d_in, const int* in_sizes, int n_in,
                              void* d_out, int out_size) {
    const float* x     = (const float*)d_in[0];
    const float* a     = (const float*)d_in[1];
    const float* b     = (const float*)d_in[2];
    const float* c     = (const float*)d_in[3];
    const float* coeff = (const float*)d_in[4];
    // d_in[5] = mf_indices: full itertools.product enumeration; digit decode analytic.
    float* out = (float*)d_out;

    prep_kernel<<<(4 * 56 * 32 + 255) / 256, 256>>>(coeff);
    anfis_hmma_kernel<<<NBLOCKS, NTHREADS, SMEM_BYTES>>>(x, a, b, c, out);
}

// round 13
// speedup vs baseline: 1.3353x; 1.0029x over previous
#include <cuda_runtime.h>
#include <cuda_bf16.h>
#include <cstdint>

#define BATCH    4096
#define MTILE    16
#define NBLOCKS  (BATCH / MTILE)   // 256
#define NTHREADS 256               // 8 warps = 8 n-chunks

// B fragments pre-laid-out for HMMA: index f=((nc*4+ks)*7+nt), lane gets
// uint4 {bh0, bh1, bl0, bl1} at g_bfrag[f*32 + lane]. 114688 B, L2-resident.
__device__ __align__(16) uint4 g_bfrag[4 * 56 * 32];

// smem byte offsets
#define OFF_AH   0                          // 16 x 128 B
#define OFF_AL   2048
#define OFF_P    4096                       // 64 x stride17 f32
#define OFF_XP   (OFF_P + 64 * 17 * 4)      // 7 x stride17 f32
#define OFF_RD   (OFF_XP + 7 * 17 * 4)      // 16 f32
#define OFF_RED  (OFF_RD + 64)              // 8 warps x 16 rows f32
#define OFF_MSM  (OFF_RED + 8 * 16 * 4)     // 24 x 16 f32
#define OFF_SS   (OFF_MSM + 24 * 16 * 4)    // 6 x 16 f32
#define SMEM_BYTES (OFF_SS + 6 * 16 * 4 + 16)

static __device__ __forceinline__ uint32_t packbf2(__nv_bfloat16 lo, __nv_bfloat16 hi) {
    __nv_bfloat162 t(lo, hi);
    return *reinterpret_cast<uint32_t*>(&t);
}
static __device__ __forceinline__ void bsplit(float v, __nv_bfloat16& h, __nv_bfloat16& l) {
    h = __float2bfloat16(v);
    l = __float2bfloat16(v - __bfloat162float(h));
}
static __device__ __forceinline__ void mma16816(float* d, const uint32_t* a,
                                                uint32_t b0, uint32_t b1) {
    asm("mma.sync.aligned.m16n8k16.row.col.f32.bf16.bf16.f32 "
        "{%0,%1,%2,%3}, {%4,%5,%6,%7}, {%8,%9}, {%0,%1,%2,%3};"
        : "+f"(d[0]), "+f"(d[1]), "+f"(d[2]), "+f"(d[3])
        : "r"(a[0]), "r"(a[1]), "r"(a[2]), "r"(a[3]), "r"(b0), "r"(b1));
}

// ---- Prep: coeff -> bf16 hi/lo fragments in exact HMMA lane layout ----
__global__ void prep_kernel(const float* __restrict__ coeff) {
    int i = blockIdx.x * blockDim.x + threadIdx.x;   // 7168 threads
    if (i >= 4 * 56 * 32) return;
    const int lane = i & 31;
    const int f    = i >> 5;
    const int nt   = f % 7;
    const int t2   = f / 7;
    const int ks   = t2 & 3;
    const int nc   = t2 >> 2;

    const int n  = nc * 56 + nt * 8 + (lane >> 2);
    const int h  = n / 7;
    const int j  = n - h * 7;
    const int k0 = ks * 16 + 2 * (lane & 3);

    float v0 = coeff[(h * 64 + k0) * 7 + j];
    float v1 = coeff[(h * 64 + k0 + 1) * 7 + j];
    float v2 = coeff[(h * 64 + k0 + 8) * 7 + j];
    float v3 = coeff[(h * 64 + k0 + 9) * 7 + j];

    __nv_bfloat16 h0, l0, h1, l1, h2, l2, h3, l3;
    bsplit(v0, h0, l0);
    bsplit(v1, h1, l1);
    bsplit(v2, h2, l2);
    bsplit(v3, h3, l3);

    uint4 o;
    o.x = packbf2(h0, h1);
    o.y = packbf2(h2, h3);
    o.z = packbf2(l0, l1);
    o.w = packbf2(l2, l3);
    g_bfrag[f * 32 + lane] = o;
}

__global__ void __launch_bounds__(NTHREADS, 2) anfis_hmma_kernel(
    const float* __restrict__ x, const float* __restrict__ a,
    const float* __restrict__ b, const float* __restrict__ c,
    float* __restrict__ out)
{
    extern __shared__ char smem[];
    float* Ps  = reinterpret_cast<float*>(smem + OFF_P);
    float* Xs  = reinterpret_cast<float*>(smem + OFF_XP);
    float* Rd  = reinterpret_cast<float*>(smem + OFF_RD);
    float* Msm = reinterpret_cast<float*>(smem + OFF_MSM);  // [(i*4+k)*16 + bl]
    float* Ss  = reinterpret_cast<float*>(smem + OFF_SS);   // [i*16 + bl]

    const int tid  = threadIdx.x;
    const int lane = tid & 31;
    const int wid  = tid >> 5;
    const int b0   = blockIdx.x * MTILE;

    // ---- Phase A: memberships, (b,i) task per thread (96 threads) ----
    if (tid < 96) {
        const int bl = tid & 15;
        const int i  = tid >> 4;       // 0..5
        float xi = __ldg(&x[(b0 + bl) * 6 + i]);
        Xs[i * 17 + bl] = xi;
        float s = 0.0f;
        #pragma unroll
        for (int k = 0; k < 4; k++) {
            float av = __ldg(&a[i * 4 + k]);
            float bv = __ldg(&b[i * 4 + k]);
            float cv = __ldg(&c[i * 4 + k]);
            float d  = __fdividef(xi - cv, av);
            float d2 = d * d;
            float db = (bv == 2.0f) ? (d2 * d2) : __powf(d2, bv);
            float mv = __fdividef(1.0f, 1.0f + db);
            Msm[(i * 4 + k) * 16 + bl] = mv;
            s += mv;
        }
        Ss[i * 16 + bl] = s;
    }
    __syncthreads();

    // ---- Phase B: den, P table, A tiles — all 256 threads ----
    if (tid < 16) {
        float den = Ss[tid] * Ss[16 + tid] * Ss[32 + tid]
                  * Ss[48 + tid] * Ss[64 + tid] * Ss[80 + tid];
        Rd[tid] = __fdividef(1.0f, fmaxf(den, 1e-12f));
        Xs[6 * 17 + tid] = 1.0f;
    }
    // P table: 1024 entries (64 h x 16 rows), 4 per thread
    #pragma unroll
    for (int q = 0; q < 4; q++) {
        const int e  = tid + q * 256;
        const int h  = e >> 4;
        const int bl = e & 15;
        Ps[h * 17 + bl] = Msm[(0 + ((h >> 4) & 3)) * 16 + bl]
                        * Msm[(4 + ((h >> 2) & 3)) * 16 + bl]
                        * Msm[(8 + (h & 3)) * 16 + bl];
    }
    // A tiles: 512 (bl, l-pair) tasks, 2 per thread
    #pragma unroll
    for (int q = 0; q < 2; q++) {
        const int u  = tid + q * 256;
        const int bl = u & 15;
        const int l  = (u >> 4) * 2;   // even l
        float tt = Msm[(12 + ((l >> 4) & 3)) * 16 + bl]
                 * Msm[(16 + ((l >> 2) & 3)) * 16 + bl];
        float q0 = tt * Msm[(20 + (l & 3)) * 16 + bl];
        float q1 = tt * Msm[(20 + ((l & 3) + 1)) * 16 + bl];
        __nv_bfloat16 h0, l0, h1, l1;
        bsplit(q0, h0, l0);
        bsplit(q1, h1, l1);
        uint32_t cb = (uint32_t)(l * 2) ^ (uint32_t)((bl & 7) << 4);
        *reinterpret_cast<uint32_t*>(smem + OFF_AH + bl * 128 + cb) = packbf2(h0, h1);
        *reinterpret_cast<uint32_t*>(smem + OFF_AL + bl * 128 + cb) = packbf2(l0, l1);
    }
    __syncthreads();

    // ---- HMMA mainloop: warp = 56-col chunk; double-buffered B from L2 ----
    const int nc = wid;

    float acc[7][4];
    #pragma unroll
    for (int nt = 0; nt < 7; nt++)
        #pragma unroll
        for (int e = 0; e < 4; e++) acc[nt][e] = 0.0f;

    const int r  = lane >> 2;
    const int c4 = (lane & 3) * 4;
    const uint32_t rsw = (uint32_t)(r << 4);

    uint4 bf[2][7];
    #pragma unroll
    for (int nt = 0; nt < 7; nt++)
        bf[0][nt] = __ldg(&g_bfrag[(((nc * 4 + 0) * 7 + nt) * 32) + lane]);

    #pragma unroll
    for (int ks = 0; ks < 4; ks++) {
        const int cur = ks & 1;
        if (ks < 3) {
            #pragma unroll
            for (int nt = 0; nt < 7; nt++)
                bf[cur ^ 1][nt] =
                    __ldg(&g_bfrag[(((nc * 4 + ks + 1) * 7 + nt) * 32) + lane]);
        }
        const uint32_t cb0 = (uint32_t)(ks * 32 + c4) ^ rsw;
        const uint32_t cb1 = (uint32_t)(ks * 32 + c4 + 16) ^ rsw;
        uint32_t ah[4], al[4];
        {
            ah[0] = *reinterpret_cast<const uint32_t*>(smem + OFF_AH + r * 128 + cb0);
            ah[1] = *reinterpret_cast<const uint32_t*>(smem + OFF_AH + (r + 8) * 128 + cb0);
            ah[2] = *reinterpret_cast<const uint32_t*>(smem + OFF_AH + r * 128 + cb1);
            ah[3] = *reinterpret_cast<const uint32_t*>(smem + OFF_AH + (r + 8) * 128 + cb1);
            al[0] = *reinterpret_cast<const uint32_t*>(smem + OFF_AL + r * 128 + cb0);
            al[1] = *reinterpret_cast<const uint32_t*>(smem + OFF_AL + (r + 8) * 128 + cb0);
            al[2] = *reinterpret_cast<const uint32_t*>(smem + OFF_AL + r * 128 + cb1);
            al[3] = *reinterpret_cast<const uint32_t*>(smem + OFF_AL + (r + 8) * 128 + cb1);
        }
        #pragma unroll
        for (int nt = 0; nt < 7; nt++) {
            mma16816(acc[nt], ah, bf[cur][nt].x, bf[cur][nt].y);   // hi*hi
            mma16816(acc[nt], ah, bf[cur][nt].z, bf[cur][nt].w);   // hi*lo
            mma16816(acc[nt], al, bf[cur][nt].x, bf[cur][nt].y);   // lo*hi
        }
    }

    // ---- Epilogue: fold P * x_plus, reduce quads, stash per-warp rows ----
    {
        float rsum[2] = {0.f, 0.f};
        #pragma unroll
        for (int nt = 0; nt < 7; nt++)
            #pragma unroll
            for (int e = 0; e < 4; e++) {
                const int row = r + (e >> 1) * 8;     // 0..15
                const int u   = nt * 8 + 2 * (lane & 3) + (e & 1);
                const int h   = u / 7;
                const int j   = u - h * 7;
                float pv = Ps[(nc * 8 + h) * 17 + row];
                float xv = Xs[j * 17 + row];
                rsum[e >> 1] = fmaf(pv * xv, acc[nt][e], rsum[e >> 1]);
            }
        #pragma unroll
        for (int i = 0; i < 2; i++) {
            rsum[i] += __shfl_xor_sync(0xFFFFFFFFu, rsum[i], 1);
            rsum[i] += __shfl_xor_sync(0xFFFFFFFFu, rsum[i], 2);
        }
        if ((lane & 3) == 0) {
            float* red = reinterpret_cast<float*>(smem + OFF_RED);
            red[wid * 16 + r]     = rsum[0];
            red[wid * 16 + r + 8] = rsum[1];
        }
    }
    __syncthreads();

    // ---- Final: sum 8 n-chunk warps per row, normalize, store ----
    if (tid < MTILE) {
        const float* red = reinterpret_cast<const float*>(smem + OFF_RED);
        float num = 0.0f;
        #pragma unroll
        for (int w = 0; w < 8; w++)
            num += red[w * 16 + tid];
        out[b0 + tid] = num * Rd[tid];
    }
}

extern "C" void kernel_launch(void* const* d_in, const int* in_sizes, int n_in,
                              void* d_out, int out_size) {
    const float* x     = (const float*)d_in[0];
    const float* a     = (const float*)d_in[1];
    const float* b     = (const float*)d_in[2];
    const float* c     = (const float*)d_in[3];
    const float* coeff = (const float*)d_in[4];
    // d_in[5] = mf_indices: full itertools.product enumeration; digit decode analytic.
    float* out = (float*)d_out;

    prep_kernel<<<(4 * 56 * 32 + 255) / 256, 256>>>(coeff);
    anfis_hmma_kernel<<<NBLOCKS, NTHREADS, SMEM_BYTES>>>(x, a, b, c, out);
}

// round 15
// speedup vs baseline: 1.3631x; 1.0208x over previous
#include <cuda_runtime.h>
#include <cuda_bf16.h>
#include <cstdint>

#define BATCH    4096
#define MTILE    16
#define NBLOCKS  (BATCH / MTILE)   // 256
#define NTHREADS 256               // 8 warps = 8 n-chunks
#define NPROD    28                // producer blocks (7168 entries / 256)

// B fragments pre-laid-out for HMMA: index f=((nc*4+ks)*7+nt), lane gets
// uint4 {bh0, bh1, bl0, bl1} at g_bfrag[f*32 + lane]. 114688 B, L2-resident.
__device__ __align__(16) uint4 g_bfrag[4 * 56 * 32];
__device__ int g_prod = 0;   // producer blocks finished
__device__ int g_done = 0;   // blocks finished (for counter reset)

// smem byte offsets
#define OFF_AH   0                          // 16 x 128 B
#define OFF_AL   2048
#define OFF_P    4096                       // 64 x stride17 f32
#define OFF_XP   (OFF_P + 64 * 17 * 4)      // 7 x stride17 f32
#define OFF_RD   (OFF_XP + 7 * 17 * 4)      // 16 f32
#define OFF_RED  (OFF_RD + 64)              // 8 warps x 16 rows f32
#define OFF_MSM  (OFF_RED + 8 * 16 * 4)     // 24 x 16 f32
#define OFF_SS   (OFF_MSM + 24 * 16 * 4)    // 6 x 16 f32
#define SMEM_BYTES (OFF_SS + 6 * 16 * 4 + 16)

static __device__ __forceinline__ uint32_t packbf2(__nv_bfloat16 lo, __nv_bfloat16 hi) {
    __nv_bfloat162 t(lo, hi);
    return *reinterpret_cast<uint32_t*>(&t);
}
static __device__ __forceinline__ void bsplit(float v, __nv_bfloat16& h, __nv_bfloat16& l) {
    h = __float2bfloat16(v);
    l = __float2bfloat16(v - __bfloat162float(h));
}
static __device__ __forceinline__ void mma16816(float* d, const uint32_t* a,
                                                uint32_t b0, uint32_t b1) {
    asm("mma.sync.aligned.m16n8k16.row.col.f32.bf16.bf16.f32 "
        "{%0,%1,%2,%3}, {%4,%5,%6,%7}, {%8,%9}, {%0,%1,%2,%3};"
        : "+f"(d[0]), "+f"(d[1]), "+f"(d[2]), "+f"(d[3])
        : "r"(a[0]), "r"(a[1]), "r"(a[2]), "r"(a[3]), "r"(b0), "r"(b1));
}
// L2-coherent 128-bit load (g_bfrag is produced DURING this kernel; the
// nc/__ldg path is only safe for launch-constant data).
static __device__ __forceinline__ uint4 ldgcg(const uint4* p) {
    uint4 v;
    asm volatile("ld.global.cg.v4.u32 {%0,%1,%2,%3}, [%4];"
                 : "=r"(v.x), "=r"(v.y), "=r"(v.z), "=r"(v.w)
                 : "l"(__cvta_generic_to_global(p)));
    return v;
}

__global__ void __launch_bounds__(NTHREADS, 2) anfis_fused_kernel(
    const float* __restrict__ x, const float* __restrict__ a,
    const float* __restrict__ b, const float* __restrict__ c,
    const float* __restrict__ coeff, float* __restrict__ out)
{
    extern __shared__ char smem[];
    float* Ps  = reinterpret_cast<float*>(smem + OFF_P);
    float* Xs  = reinterpret_cast<float*>(smem + OFF_XP);
    float* Rd  = reinterpret_cast<float*>(smem + OFF_RD);
    float* Msm = reinterpret_cast<float*>(smem + OFF_MSM);  // [(i*4+k)*16 + bl]
    float* Ss  = reinterpret_cast<float*>(smem + OFF_SS);   // [i*16 + bl]

    const int tid  = threadIdx.x;
    const int lane = tid & 31;
    const int wid  = tid >> 5;
    const int bid  = blockIdx.x;
    const int b0   = bid * MTILE;

    // ---- Producer phase (blocks 0..27): convert coeff slice -> g_bfrag ----
    if (bid < NPROD) {
        const int e   = bid * NTHREADS + tid;   // 0..7167
        const int el  = e & 31;
        const int f   = e >> 5;
        const int nt  = f % 7;
        const int t2  = f / 7;
        const int ks  = t2 & 3;
        const int nc  = t2 >> 2;
        const int n   = nc * 56 + nt * 8 + (el >> 2);
        const int h   = n / 7;
        const int j   = n - h * 7;
        const int k0  = ks * 16 + 2 * (el & 3);

        float v0 = __ldg(&coeff[(h * 64 + k0) * 7 + j]);
        float v1 = __ldg(&coeff[(h * 64 + k0 + 1) * 7 + j]);
        float v2 = __ldg(&coeff[(h * 64 + k0 + 8) * 7 + j]);
        float v3 = __ldg(&coeff[(h * 64 + k0 + 9) * 7 + j]);

        __nv_bfloat16 h0, l0, h1, l1, h2, l2, h3, l3;
        bsplit(v0, h0, l0);
        bsplit(v1, h1, l1);
        bsplit(v2, h2, l2);
        bsplit(v3, h3, l3);

        uint4 o;
        o.x = packbf2(h0, h1);
        o.y = packbf2(h2, h3);
        o.z = packbf2(l0, l1);
        o.w = packbf2(l2, l3);
        g_bfrag[f * 32 + el] = o;

        __syncthreads();            // all stores of this block done
        if (tid == 0) {
            __threadfence();        // publish before signaling
            atomicAdd(&g_prod, 1);
        }
    }

    // ---- Phase A: memberships, (b,i) task per thread (96 threads) ----
    if (tid < 96) {
        const int bl = tid & 15;
        const int i  = tid >> 4;       // 0..5
        float xi = __ldg(&x[(b0 + bl) * 6 + i]);
        Xs[i * 17 + bl] = xi;
        float s = 0.0f;
        #pragma unroll
        for (int k = 0; k < 4; k++) {
            float av = __ldg(&a[i * 4 + k]);
            float bv = __ldg(&b[i * 4 + k]);
            float cv = __ldg(&c[i * 4 + k]);
            float d  = __fdividef(xi - cv, av);
            float d2 = d * d;
            float db = (bv == 2.0f) ? (d2 * d2) : __powf(d2, bv);
            float mv = __fdividef(1.0f, 1.0f + db);
            Msm[(i * 4 + k) * 16 + bl] = mv;
            s += mv;
        }
        Ss[i * 16 + bl] = s;
    }
    __syncthreads();

    // ---- Phase B: den, P table, A tiles — all 256 threads ----
    if (tid < 16) {
        float den = Ss[tid] * Ss[16 + tid] * Ss[32 + tid]
                  * Ss[48 + tid] * Ss[64 + tid] * Ss[80 + tid];
        Rd[tid] = __fdividef(1.0f, fmaxf(den, 1e-12f));
        Xs[6 * 17 + tid] = 1.0f;
    }
    #pragma unroll
    for (int q = 0; q < 4; q++) {
        const int e  = tid + q * 256;
        const int h  = e >> 4;
        const int bl = e & 15;
        Ps[h * 17 + bl] = Msm[(0 + ((h >> 4) & 3)) * 16 + bl]
                        * Msm[(4 + ((h >> 2) & 3)) * 16 + bl]
                        * Msm[(8 + (h & 3)) * 16 + bl];
    }
    #pragma unroll
    for (int q = 0; q < 2; q++) {
        const int u  = tid + q * 256;
        const int bl = u & 15;
        const int l  = (u >> 4) * 2;   // even l
        float tt = Msm[(12 + ((l >> 4) & 3)) * 16 + bl]
                 * Msm[(16 + ((l >> 2) & 3)) * 16 + bl];
        float q0 = tt * Msm[(20 + (l & 3)) * 16 + bl];
        float q1 = tt * Msm[(20 + ((l & 3) + 1)) * 16 + bl];
        __nv_bfloat16 h0, l0, h1, l1;
        bsplit(q0, h0, l0);
        bsplit(q1, h1, l1);
        uint32_t cb = (uint32_t)(l * 2) ^ (uint32_t)((bl & 7) << 4);
        *reinterpret_cast<uint32_t*>(smem + OFF_AH + bl * 128 + cb) = packbf2(h0, h1);
        *reinterpret_cast<uint32_t*>(smem + OFF_AL + bl * 128 + cb) = packbf2(l0, l1);
    }

    // ---- Inter-block barrier: wait for all producer slices ----
    if (tid == 0) {
        while (atomicAdd(&g_prod, 0) < NPROD) {}
        __threadfence();
    }
    __syncthreads();   // exec + memory barrier: no consumer load hoists above

    // ---- HMMA mainloop: warp = 56-col chunk; double-buffered B via L2 (.cg) ----
    const int nc = wid;

    float acc[7][4];
    #pragma unroll
    for (int nt = 0; nt < 7; nt++)
        #pragma unroll
        for (int e = 0; e < 4; e++) acc[nt][e] = 0.0f;

    const int r  = lane >> 2;
    const int c4 = (lane & 3) * 4;
    const uint32_t rsw = (uint32_t)(r << 4);

    uint4 bf[2][7];
    #pragma unroll
    for (int nt = 0; nt < 7; nt++)
        bf[0][nt] = ldgcg(&g_bfrag[(((nc * 4 + 0) * 7 + nt) * 32) + lane]);

    #pragma unroll
    for (int ks = 0; ks < 4; ks++) {
        const int cur = ks & 1;
        if (ks < 3) {
            #pragma unroll
            for (int nt = 0; nt < 7; nt++)
                bf[cur ^ 1][nt] =
                    ldgcg(&g_bfrag[(((nc * 4 + ks + 1) * 7 + nt) * 32) + lane]);
        }
        const uint32_t cb0 = (uint32_t)(ks * 32 + c4) ^ rsw;
        const uint32_t cb1 = (uint32_t)(ks * 32 + c4 + 16) ^ rsw;
        uint32_t ah[4], al[4];
        {
            ah[0] = *reinterpret_cast<const uint32_t*>(smem + OFF_AH + r * 128 + cb0);
            ah[1] = *reinterpret_cast<const uint32_t*>(smem + OFF_AH + (r + 8) * 128 + cb0);
            ah[2] = *reinterpret_cast<const uint32_t*>(smem + OFF_AH + r * 128 + cb1);
            ah[3] = *reinterpret_cast<const uint32_t*>(smem + OFF_AH + (r + 8) * 128 + cb1);
            al[0] = *reinterpret_cast<const uint32_t*>(smem + OFF_AL + r * 128 + cb0);
            al[1] = *reinterpret_cast<const uint32_t*>(smem + OFF_AL + (r + 8) * 128 + cb0);
            al[2] = *reinterpret_cast<const uint32_t*>(smem + OFF_AL + r * 128 + cb1);
            al[3] = *reinterpret_cast<const uint32_t*>(smem + OFF_AL + (r + 8) * 128 + cb1);
        }
        #pragma unroll
        for (int nt = 0; nt < 7; nt++) {
            mma16816(acc[nt], ah, bf[cur][nt].x, bf[cur][nt].y);   // hi*hi
            mma16816(acc[nt], ah, bf[cur][nt].z, bf[cur][nt].w);   // hi*lo
            mma16816(acc[nt], al, bf[cur][nt].x, bf[cur][nt].y);   // lo*hi
        }
    }

    // ---- Epilogue: fold P * x_plus, reduce quads, stash per-warp rows ----
    {
        float rsum[2] = {0.f, 0.f};
        #pragma unroll
        for (int nt = 0; nt < 7; nt++)
            #pragma unroll
            for (int e = 0; e < 4; e++) {
                const int row = r + (e >> 1) * 8;     // 0..15
                const int u   = nt * 8 + 2 * (lane & 3) + (e & 1);
                const int h   = u / 7;
                const int j   = u - h * 7;
                float pv = Ps[(nc * 8 + h) * 17 + row];
                float xv = Xs[j * 17 + row];
                rsum[e >> 1] = fmaf(pv * xv, acc[nt][e], rsum[e >> 1]);
            }
        #pragma unroll
        for (int i = 0; i < 2; i++) {
            rsum[i] += __shfl_xor_sync(0xFFFFFFFFu, rsum[i], 1);
            rsum[i] += __shfl_xor_sync(0xFFFFFFFFu, rsum[i], 2);
        }
        if ((lane & 3) == 0) {
            float* red = reinterpret_cast<float*>(smem + OFF_RED);
            red[wid * 16 + r]     = rsum[0];
            red[wid * 16 + r + 8] = rsum[1];
        }
    }
    __syncthreads();

    // ---- Final: sum 8 n-chunk warps per row, normalize, store ----
    if (tid < MTILE) {
        const float* red = reinterpret_cast<const float*>(smem + OFF_RED);
        float num = 0.0f;
        #pragma unroll
        for (int w = 0; w < 8; w++)
            num += red[w * 16 + tid];
        out[b0 + tid] = num * Rd[tid];
    }

    // ---- Counter reset (last block through restores g_prod/g_done = 0) ----
    if (tid == 0) {
        int d = atomicAdd(&g_done, 1);
        if (d == NBLOCKS - 1) {
            atomicExch(&g_prod, 0);
            atomicExch(&g_done, 0);
        }
    }
}

extern "C" void kernel_launch(void* const* d_in, const int* in_sizes, int n_in,
                              void* d_out, int out_size) {
    const float* x     = (const float*)d_in[0];
    const float* a     = (const float*)d_in[1];
    const float* b     = (const float*)d_in[2];
    const float* c     = (const float*)d_in[3];
    const float* coeff = (const float*)d_in[4];
    // d_in[5] = mf_indices: full itertools.product enumeration; digit decode analytic.
    float* out = (float*)d_out;

    anfis_fused_kernel<<<NBLOCKS, NTHREADS, SMEM_BYTES>>>(x, a, b, c, coeff, out);
}